// round 1
// baseline (speedup 1.0000x reference)
#include <cuda_runtime.h>
#include <math.h>

#define N_TOK 8192
#define DIM   1024

// Scratch (static __device__ arrays: allowed; no runtime allocation)
__device__ float g_Q[(size_t)N_TOK * DIM];
__device__ float g_K[(size_t)N_TOK * DIM];
__device__ float g_V[(size_t)N_TOK * DIM];
__device__ float g_S[(size_t)N_TOK * N_TOK];

#define BM 128
#define BN 128
#define BK 8
#define TM 8
#define TN 8
#define PAD 4

// C[M,N] = A[M,K] * B[N,K]^T   (both row-major, K contiguous in both)
__global__ void __launch_bounds__(256) sgemm_abt(const float* __restrict__ A,
                                                 const float* __restrict__ B,
                                                 float* __restrict__ C,
                                                 int M, int N, int K)
{
    __shared__ float As[BK][BM + PAD];
    __shared__ float Bs[BK][BN + PAD];

    const int tid = threadIdx.x;
    const int m0 = blockIdx.y * BM;
    const int n0 = blockIdx.x * BN;

    const int lrow = tid >> 1;         // 0..127
    const int lk4  = (tid & 1) * 4;    // 0 or 4

    const int tx = tid & 15;           // 0..15 -> N
    const int ty = tid >> 4;           // 0..15 -> M

    float acc[TM][TN];
#pragma unroll
    for (int i = 0; i < TM; i++)
#pragma unroll
        for (int j = 0; j < TN; j++) acc[i][j] = 0.0f;

    for (int k0 = 0; k0 < K; k0 += BK) {
        float4 av = *(const float4*)(A + (size_t)(m0 + lrow) * K + k0 + lk4);
        float4 bv = *(const float4*)(B + (size_t)(n0 + lrow) * K + k0 + lk4);
        __syncthreads();   // previous iteration's compute done before overwrite
        As[lk4 + 0][lrow] = av.x;
        As[lk4 + 1][lrow] = av.y;
        As[lk4 + 2][lrow] = av.z;
        As[lk4 + 3][lrow] = av.w;
        Bs[lk4 + 0][lrow] = bv.x;
        Bs[lk4 + 1][lrow] = bv.y;
        Bs[lk4 + 2][lrow] = bv.z;
        Bs[lk4 + 3][lrow] = bv.w;
        __syncthreads();

#pragma unroll
        for (int kk = 0; kk < BK; kk++) {
            float4 a0 = *(const float4*)&As[kk][ty * TM];
            float4 a1 = *(const float4*)&As[kk][ty * TM + 4];
            float4 b0 = *(const float4*)&Bs[kk][tx * TN];
            float4 b1 = *(const float4*)&Bs[kk][tx * TN + 4];
            float a[TM] = {a0.x, a0.y, a0.z, a0.w, a1.x, a1.y, a1.z, a1.w};
            float b[TN] = {b0.x, b0.y, b0.z, b0.w, b1.x, b1.y, b1.z, b1.w};
#pragma unroll
            for (int i = 0; i < TM; i++)
#pragma unroll
                for (int j = 0; j < TN; j++)
                    acc[i][j] = fmaf(a[i], b[j], acc[i][j]);
        }
    }

#pragma unroll
    for (int i = 0; i < TM; i++) {
        float* crow = C + (size_t)(m0 + ty * TM + i) * N + n0 + tx * TN;
        float4 v0 = make_float4(acc[i][0], acc[i][1], acc[i][2], acc[i][3]);
        float4 v1 = make_float4(acc[i][4], acc[i][5], acc[i][6], acc[i][7]);
        *(float4*)(crow)     = v0;
        *(float4*)(crow + 4) = v1;
    }
}

// C[M,N] = A[M,K] * B[K,N]   (row-major; N contiguous in B)
__global__ void __launch_bounds__(256) sgemm_abn(const float* __restrict__ A,
                                                 const float* __restrict__ B,
                                                 float* __restrict__ C,
                                                 int M, int N, int K)
{
    __shared__ float As[BK][BM + PAD];
    __shared__ float Bs[BK][BN + PAD];

    const int tid = threadIdx.x;
    const int m0 = blockIdx.y * BM;
    const int n0 = blockIdx.x * BN;

    const int lrow = tid >> 1;         // A loader: 0..127
    const int lk4  = (tid & 1) * 4;

    const int brow = tid >> 5;         // B loader: 0..7 (k)
    const int bcol = (tid & 31) * 4;   // 0..124 (n)

    const int tx = tid & 15;
    const int ty = tid >> 4;

    float acc[TM][TN];
#pragma unroll
    for (int i = 0; i < TM; i++)
#pragma unroll
        for (int j = 0; j < TN; j++) acc[i][j] = 0.0f;

    for (int k0 = 0; k0 < K; k0 += BK) {
        float4 av = *(const float4*)(A + (size_t)(m0 + lrow) * K + k0 + lk4);
        float4 bv = *(const float4*)(B + (size_t)(k0 + brow) * N + n0 + bcol);
        __syncthreads();
        As[lk4 + 0][lrow] = av.x;
        As[lk4 + 1][lrow] = av.y;
        As[lk4 + 2][lrow] = av.z;
        As[lk4 + 3][lrow] = av.w;
        *(float4*)&Bs[brow][bcol] = bv;
        __syncthreads();

#pragma unroll
        for (int kk = 0; kk < BK; kk++) {
            float4 a0 = *(const float4*)&As[kk][ty * TM];
            float4 a1 = *(const float4*)&As[kk][ty * TM + 4];
            float4 b0 = *(const float4*)&Bs[kk][tx * TN];
            float4 b1 = *(const float4*)&Bs[kk][tx * TN + 4];
            float a[TM] = {a0.x, a0.y, a0.z, a0.w, a1.x, a1.y, a1.z, a1.w};
            float b[TN] = {b0.x, b0.y, b0.z, b0.w, b1.x, b1.y, b1.z, b1.w};
#pragma unroll
            for (int i = 0; i < TM; i++)
#pragma unroll
                for (int j = 0; j < TN; j++)
                    acc[i][j] = fmaf(a[i], b[j], acc[i][j]);
        }
    }

#pragma unroll
    for (int i = 0; i < TM; i++) {
        float* crow = C + (size_t)(m0 + ty * TM + i) * N + n0 + tx * TN;
        float4 v0 = make_float4(acc[i][0], acc[i][1], acc[i][2], acc[i][3]);
        float4 v1 = make_float4(acc[i][4], acc[i][5], acc[i][6], acc[i][7]);
        *(float4*)(crow)     = v0;
        *(float4*)(crow + 4) = v1;
    }
}

// In-place row softmax over N_TOK columns, one block per row.
__global__ void __launch_bounds__(256) softmax_rows(float* __restrict__ S)
{
    const int row = blockIdx.x;
    float4* p = (float4*)(S + (size_t)row * N_TOK);
    const int n4 = N_TOK / 4;   // 2048
    const int tid = threadIdx.x;

    __shared__ float red[8];
    __shared__ float bcast;

    // --- max ---
    float m = -1e30f;
    for (int i = tid; i < n4; i += 256) {
        float4 v = p[i];
        m = fmaxf(m, fmaxf(fmaxf(v.x, v.y), fmaxf(v.z, v.w)));
    }
#pragma unroll
    for (int o = 16; o > 0; o >>= 1) m = fmaxf(m, __shfl_xor_sync(0xffffffffu, m, o));
    if ((tid & 31) == 0) red[tid >> 5] = m;
    __syncthreads();
    if (tid == 0) {
        float t = red[0];
#pragma unroll
        for (int i = 1; i < 8; i++) t = fmaxf(t, red[i]);
        bcast = t;
    }
    __syncthreads();
    const float rowmax = bcast;
    __syncthreads();

    // --- exp + sum ---
    float s = 0.0f;
    for (int i = tid; i < n4; i += 256) {
        float4 v = p[i];
        v.x = __expf(v.x - rowmax);
        v.y = __expf(v.y - rowmax);
        v.z = __expf(v.z - rowmax);
        v.w = __expf(v.w - rowmax);
        p[i] = v;
        s += v.x + v.y + v.z + v.w;
    }
#pragma unroll
    for (int o = 16; o > 0; o >>= 1) s += __shfl_xor_sync(0xffffffffu, s, o);
    if ((tid & 31) == 0) red[tid >> 5] = s;
    __syncthreads();
    if (tid == 0) {
        float t = 0.0f;
#pragma unroll
        for (int i = 0; i < 8; i++) t += red[i];
        bcast = 1.0f / t;
    }
    __syncthreads();
    const float inv = bcast;

    // --- normalize ---
    for (int i = tid; i < n4; i += 256) {
        float4 v = p[i];
        v.x *= inv; v.y *= inv; v.z *= inv; v.w *= inv;
        p[i] = v;
    }
}

extern "C" void kernel_launch(void* const* d_in, const int* in_sizes, int n_in,
                              void* d_out, int out_size)
{
    const float* X  = (const float*)d_in[0];
    const float* Wq = (const float*)d_in[1];
    const float* Wk = (const float*)d_in[2];
    const float* Wv = (const float*)d_in[3];
    float* O = (float*)d_out;

    float *Q, *K, *V, *S;
    cudaGetSymbolAddress((void**)&Q, g_Q);
    cudaGetSymbolAddress((void**)&K, g_K);
    cudaGetSymbolAddress((void**)&V, g_V);
    cudaGetSymbolAddress((void**)&S, g_S);

    dim3 blk(256);

    // QKV projections: C = X * W^T   [8192,1024] x [1024,1024]^T
    dim3 gqkv(DIM / BN, N_TOK / BM);
    sgemm_abt<<<gqkv, blk>>>(X, Wq, Q, N_TOK, DIM, DIM);
    sgemm_abt<<<gqkv, blk>>>(X, Wk, K, N_TOK, DIM, DIM);
    sgemm_abt<<<gqkv, blk>>>(X, Wv, V, N_TOK, DIM, DIM);

    // S = Q * K^T   [8192,8192]
    dim3 gs(N_TOK / BN, N_TOK / BM);
    sgemm_abt<<<gs, blk>>>(Q, K, S, N_TOK, N_TOK, DIM);

    // softmax rows, in place
    softmax_rows<<<N_TOK, blk>>>(S);

    // O = P * V   [8192,8192] x [8192,1024]
    dim3 go(DIM / BN, N_TOK / BM);
    sgemm_abn<<<go, blk>>>(S, V, O, N_TOK, DIM, N_TOK);
}

// round 7
// speedup vs baseline: 2.7030x; 2.7030x over previous
#include <cuda_runtime.h>
#include <cuda_bf16.h>
#include <cstdint>
#include <cstddef>
#include <math.h>

#define N_TOK 8192
#define DIM   1024

typedef __nv_bfloat16 bf16;
typedef __nv_bfloat162 bf162;
typedef unsigned int u32;

// ---- scratch (static device arrays; no runtime allocation) ----
__device__ bf16 g_Xh[(size_t)N_TOK * DIM];
__device__ bf16 g_Xl[(size_t)N_TOK * DIM];
__device__ bf16 g_Wqh[DIM * DIM];
__device__ bf16 g_Wql[DIM * DIM];
__device__ bf16 g_Wkh[DIM * DIM];
__device__ bf16 g_Wkl[DIM * DIM];
__device__ bf16 g_Wvh[DIM * DIM];
__device__ bf16 g_Wvl[DIM * DIM];
__device__ bf16 g_Qh[(size_t)N_TOK * DIM];
__device__ bf16 g_Ql[(size_t)N_TOK * DIM];
__device__ bf16 g_Kh[(size_t)N_TOK * DIM];
__device__ bf16 g_Kl[(size_t)N_TOK * DIM];
__device__ bf16 g_Vh[(size_t)N_TOK * DIM];
__device__ bf16 g_Vl[(size_t)N_TOK * DIM];
__device__ float g_S[(size_t)N_TOK * N_TOK];
__device__ bf16 g_Ph[(size_t)N_TOK * N_TOK];
__device__ bf16 g_Pl[(size_t)N_TOK * N_TOK];

// ---- PTX helpers ----
__device__ __forceinline__ u32 smem_u32(const void* p) {
    return (u32)__cvta_generic_to_shared(p);
}
__device__ __forceinline__ void cp_async16(u32 dst, const void* src) {
    asm volatile("cp.async.cg.shared.global [%0], [%1], 16;" :: "r"(dst), "l"(src));
}
__device__ __forceinline__ void cp_commit() { asm volatile("cp.async.commit_group;"); }
__device__ __forceinline__ void cp_wait0()  { asm volatile("cp.async.wait_group 0;"); }

__device__ __forceinline__ void ldsm4(u32& r0, u32& r1, u32& r2, u32& r3, u32 addr) {
    asm volatile("ldmatrix.sync.aligned.m8n8.x4.shared.b16 {%0,%1,%2,%3}, [%4];"
                 : "=r"(r0), "=r"(r1), "=r"(r2), "=r"(r3) : "r"(addr));
}
__device__ __forceinline__ void ldsm4t(u32& r0, u32& r1, u32& r2, u32& r3, u32 addr) {
    asm volatile("ldmatrix.sync.aligned.m8n8.x4.trans.shared.b16 {%0,%1,%2,%3}, [%4];"
                 : "=r"(r0), "=r"(r1), "=r"(r2), "=r"(r3) : "r"(addr));
}
__device__ __forceinline__ void mma16816(float* c, const u32* a, const u32* b) {
    asm volatile("mma.sync.aligned.m16n8k16.row.col.f32.bf16.bf16.f32 "
                 "{%0,%1,%2,%3}, {%4,%5,%6,%7}, {%8,%9}, {%0,%1,%2,%3};"
                 : "+f"(c[0]), "+f"(c[1]), "+f"(c[2]), "+f"(c[3])
                 : "r"(a[0]), "r"(a[1]), "r"(a[2]), "r"(a[3]), "r"(b[0]), "r"(b[1]));
}

__device__ __forceinline__ u32 swz128(u32 off) { return off ^ (((off >> 7) & 7u) << 4); }
__device__ __forceinline__ u32 swz256(u32 off) { return off ^ (((off >> 8) & 7u) << 4); }

// ---- fp32 -> (hi, lo) bf16 split ----
__global__ void __launch_bounds__(256) split_f32(const float* __restrict__ x,
                                                 bf16* __restrict__ h, bf16* __restrict__ l,
                                                 size_t n)
{
    size_t i = (size_t)blockIdx.x * blockDim.x + threadIdx.x;
    if (i < n) {
        float v = x[i];
        bf16 hi = __float2bfloat16(v);
        h[i] = hi;
        l[i] = __float2bfloat16(v - __bfloat162float(hi));
    }
}

// ---- stage loader for the GEMM (A always [M][K]; B layout per brow) ----
__device__ __forceinline__ void load_stage(
    u32 sb, int brow,
    const bf16* Ah, const bf16* Al, const bf16* Bh, const bf16* Bl,
    int m0, int n0, int kt, int Kd, int Nd, int tid)
{
    for (int c = tid; c < 1024; c += 256) {
        int row = c >> 3;
        int cc = c & 7;
        u32 d = sb + swz128((u32)(row * 128 + cc * 16));
        size_t g = (size_t)(m0 + row) * Kd + (size_t)kt * 64 + cc * 8;
        cp_async16(d, Ah + g);
        cp_async16(d + 16384u, Al + g);
    }
    if (!brow) {
        for (int c = tid; c < 1024; c += 256) {
            int row = c >> 3;
            int cc = c & 7;
            u32 d = sb + 32768u + swz128((u32)(row * 128 + cc * 16));
            size_t g = (size_t)(n0 + row) * Kd + (size_t)kt * 64 + cc * 8;
            cp_async16(d, Bh + g);
            cp_async16(d + 16384u, Bl + g);
        }
    } else {
        for (int c = tid; c < 1024; c += 256) {
            int row = c >> 4;
            int cc = c & 15;
            u32 d = sb + 32768u + swz256((u32)(row * 256 + cc * 16));
            size_t g = (size_t)((size_t)kt * 64 + row) * Nd + n0 + cc * 8;
            cp_async16(d, Bh + g);
            cp_async16(d + 16384u, Bl + g);
        }
    }
}

// ============================================================================
// Split-bf16 GEMM: C[M,N] = A[M,K] * B
//   brow=0: B stored [N][K] (C = A * B^T)     -> ldmatrix
//   brow=1: B stored [K][N] (N contiguous)    -> ldmatrix.trans
//   splitout=1: write C as (hi, lo) bf16; else fp32
// Tiles: 128x128x64, 256 threads, warp grid 2x4, warp tile 64x32.
// SMEM per stage: AH(16K) AL(16K) BH(16K) BL(16K) = 64K, 2 stages = 128K.
// ============================================================================
__global__ void __launch_bounds__(256) gemm_sp(
    const bf16* __restrict__ Ah, const bf16* __restrict__ Al,
    const bf16* __restrict__ Bh, const bf16* __restrict__ Bl,
    float* __restrict__ Cf, bf16* __restrict__ Ch, bf16* __restrict__ Cl,
    int M, int Nd, int Kd, int brow, int splitout)
{
    extern __shared__ char smem[];
    const int tid  = threadIdx.x;
    const int lane = tid & 31;
    const int warp = tid >> 5;
    const int wm   = warp >> 2;
    const int wn   = warp & 3;
    const int m0   = blockIdx.y * 128;
    const int n0   = blockIdx.x * 128;
    const u32 sbase = smem_u32(smem);

    float acc[4][4][4];
#pragma unroll
    for (int i = 0; i < 4; i++) {
#pragma unroll
        for (int j = 0; j < 4; j++) {
#pragma unroll
            for (int k = 0; k < 4; k++) {
                acc[i][j][k] = 0.0f;
            }
        }
    }

    const int KT = Kd >> 6;

    load_stage(sbase, brow, Ah, Al, Bh, Bl, m0, n0, 0, Kd, Nd, tid);
    cp_commit();

    for (int kt = 0; kt < KT; kt++) {
        const int cur = kt & 1;
        cp_wait0();
        __syncthreads();
        if (kt + 1 < KT) {
            load_stage(sbase + (u32)(cur ^ 1) * 65536u, brow,
                       Ah, Al, Bh, Bl, m0, n0, kt + 1, Kd, Nd, tid);
            cp_commit();
        }

        const u32 sA = sbase + (u32)cur * 65536u;
        const u32 sB = sA + 32768u;

#pragma unroll
        for (int ks = 0; ks < 4; ks++) {
            u32 ah[4][4];
            u32 al[4][4];
            u32 bh[4][2];
            u32 bl[4][2];
#pragma unroll
            for (int mt = 0; mt < 4; mt++) {
                int row  = wm * 64 + mt * 16 + (lane & 15);
                int colb = (ks * 16 + ((lane >> 4) << 3)) * 2;
                u32 ad = sA + swz128((u32)(row * 128 + colb));
                ldsm4(ah[mt][0], ah[mt][1], ah[mt][2], ah[mt][3], ad);
                ldsm4(al[mt][0], al[mt][1], al[mt][2], al[mt][3], ad + 16384u);
            }
            if (!brow) {
#pragma unroll
                for (int pr = 0; pr < 2; pr++) {
                    int rowN = wn * 32 + pr * 16 + (lane & 7) + ((lane >> 4) << 3);
                    int colb = (ks * 16 + (((lane >> 3) & 1) << 3)) * 2;
                    u32 ad = sB + swz128((u32)(rowN * 128 + colb));
                    ldsm4(bh[pr * 2][0], bh[pr * 2][1], bh[pr * 2 + 1][0], bh[pr * 2 + 1][1], ad);
                    ldsm4(bl[pr * 2][0], bl[pr * 2][1], bl[pr * 2 + 1][0], bl[pr * 2 + 1][1], ad + 16384u);
                }
            } else {
#pragma unroll
                for (int pr = 0; pr < 2; pr++) {
                    int rowK = ks * 16 + (lane & 15);
                    int coln = wn * 32 + pr * 16 + ((lane >> 4) << 3);
                    u32 ad = sB + swz256((u32)(rowK * 256 + coln * 2));
                    ldsm4t(bh[pr * 2][0], bh[pr * 2][1], bh[pr * 2 + 1][0], bh[pr * 2 + 1][1], ad);
                    ldsm4t(bl[pr * 2][0], bl[pr * 2][1], bl[pr * 2 + 1][0], bl[pr * 2 + 1][1], ad + 16384u);
                }
            }
#pragma unroll
            for (int mt = 0; mt < 4; mt++) {
#pragma unroll
                for (int nt = 0; nt < 4; nt++) {
                    mma16816(acc[mt][nt], ah[mt], bh[nt]);
                }
            }
#pragma unroll
            for (int mt = 0; mt < 4; mt++) {
#pragma unroll
                for (int nt = 0; nt < 4; nt++) {
                    mma16816(acc[mt][nt], ah[mt], bl[nt]);
                }
            }
#pragma unroll
            for (int mt = 0; mt < 4; mt++) {
#pragma unroll
                for (int nt = 0; nt < 4; nt++) {
                    mma16816(acc[mt][nt], al[mt], bh[nt]);
                }
            }
        }
        __syncthreads();
    }

    // ---- epilogue ----
#pragma unroll
    for (int mt = 0; mt < 4; mt++) {
#pragma unroll
        for (int nt = 0; nt < 4; nt++) {
            int row = m0 + wm * 64 + mt * 16 + (lane >> 2);
            int col = n0 + wn * 32 + nt * 8 + (lane & 3) * 2;
            const float* c = acc[mt][nt];
            size_t i0 = (size_t)row * Nd + col;
            size_t i1 = (size_t)(row + 8) * Nd + col;
            if (splitout) {
                bf16 h0 = __float2bfloat16(c[0]);
                bf16 h1 = __float2bfloat16(c[1]);
                bf16 h2 = __float2bfloat16(c[2]);
                bf16 h3 = __float2bfloat16(c[3]);
                bf162 hp0;
                hp0.x = h0;
                hp0.y = h1;
                bf162 hp1;
                hp1.x = h2;
                hp1.y = h3;
                *(bf162*)(Ch + i0) = hp0;
                *(bf162*)(Ch + i1) = hp1;
                bf162 lp0;
                bf162 lp1;
                lp0.x = __float2bfloat16(c[0] - __bfloat162float(h0));
                lp0.y = __float2bfloat16(c[1] - __bfloat162float(h1));
                lp1.x = __float2bfloat16(c[2] - __bfloat162float(h2));
                lp1.y = __float2bfloat16(c[3] - __bfloat162float(h3));
                *(bf162*)(Cl + i0) = lp0;
                *(bf162*)(Cl + i1) = lp1;
            } else {
                *(float2*)(Cf + i0) = make_float2(c[0], c[1]);
                *(float2*)(Cf + i1) = make_float2(c[2], c[3]);
            }
        }
    }
}

// ---- row softmax: fp32 in, (hi, lo) bf16 out ----
__global__ void __launch_bounds__(256) softmax_rows(float* __restrict__ S,
                                                    bf16* __restrict__ Ph,
                                                    bf16* __restrict__ Pl)
{
    const int row = blockIdx.x;
    float4* p = (float4*)(S + (size_t)row * N_TOK);
    const int n4 = N_TOK / 4;
    const int tid = threadIdx.x;

    __shared__ float red[8];
    __shared__ float bcast;

    float m = -1e30f;
    for (int i = tid; i < n4; i += 256) {
        float4 v = p[i];
        m = fmaxf(m, fmaxf(fmaxf(v.x, v.y), fmaxf(v.z, v.w)));
    }
#pragma unroll
    for (int o = 16; o > 0; o >>= 1) {
        m = fmaxf(m, __shfl_xor_sync(0xffffffffu, m, o));
    }
    if ((tid & 31) == 0) {
        red[tid >> 5] = m;
    }
    __syncthreads();
    if (tid == 0) {
        float t = red[0];
#pragma unroll
        for (int i = 1; i < 8; i++) {
            t = fmaxf(t, red[i]);
        }
        bcast = t;
    }
    __syncthreads();
    const float rowmax = bcast;
    __syncthreads();

    float s = 0.0f;
    for (int i = tid; i < n4; i += 256) {
        float4 v = p[i];
        v.x = __expf(v.x - rowmax);
        v.y = __expf(v.y - rowmax);
        v.z = __expf(v.z - rowmax);
        v.w = __expf(v.w - rowmax);
        p[i] = v;
        s += v.x + v.y + v.z + v.w;
    }
#pragma unroll
    for (int o = 16; o > 0; o >>= 1) {
        s += __shfl_xor_sync(0xffffffffu, s, o);
    }
    if ((tid & 31) == 0) {
        red[tid >> 5] = s;
    }
    __syncthreads();
    if (tid == 0) {
        float t = 0.0f;
#pragma unroll
        for (int i = 0; i < 8; i++) {
            t += red[i];
        }
        bcast = 1.0f / t;
    }
    __syncthreads();
    const float inv = bcast;

    bf162* ph = (bf162*)(Ph + (size_t)row * N_TOK);
    bf162* pl = (bf162*)(Pl + (size_t)row * N_TOK);
    for (int i = tid; i < n4; i += 256) {
        float4 v = p[i];
        v.x *= inv;
        v.y *= inv;
        v.z *= inv;
        v.w *= inv;
        bf16 h0 = __float2bfloat16(v.x);
        bf16 h1 = __float2bfloat16(v.y);
        bf16 h2 = __float2bfloat16(v.z);
        bf16 h3 = __float2bfloat16(v.w);
        bf162 a;
        a.x = h0;
        a.y = h1;
        bf162 b;
        b.x = h2;
        b.y = h3;
        ph[2 * i] = a;
        ph[2 * i + 1] = b;
        bf162 cc;
        bf162 dd;
        cc.x = __float2bfloat16(v.x - __bfloat162float(h0));
        cc.y = __float2bfloat16(v.y - __bfloat162float(h1));
        dd.x = __float2bfloat16(v.z - __bfloat162float(h2));
        dd.y = __float2bfloat16(v.w - __bfloat162float(h3));
        pl[2 * i] = cc;
        pl[2 * i + 1] = dd;
    }
}

extern "C" void kernel_launch(void* const* d_in, const int* in_sizes, int n_in,
                              void* d_out, int out_size)
{
    const float* X  = (const float*)d_in[0];
    const float* Wq = (const float*)d_in[1];
    const float* Wk = (const float*)d_in[2];
    const float* Wv = (const float*)d_in[3];
    float* O = (float*)d_out;

    bf16* Xh;  bf16* Xl;
    bf16* Wqh; bf16* Wql;
    bf16* Wkh; bf16* Wkl;
    bf16* Wvh; bf16* Wvl;
    bf16* Qh;  bf16* Ql;
    bf16* Kh;  bf16* Kl;
    bf16* Vh;  bf16* Vl;
    bf16* Ph;  bf16* Pl;
    float* S;
    cudaGetSymbolAddress((void**)&Xh, g_Xh);
    cudaGetSymbolAddress((void**)&Xl, g_Xl);
    cudaGetSymbolAddress((void**)&Wqh, g_Wqh);
    cudaGetSymbolAddress((void**)&Wql, g_Wql);
    cudaGetSymbolAddress((void**)&Wkh, g_Wkh);
    cudaGetSymbolAddress((void**)&Wkl, g_Wkl);
    cudaGetSymbolAddress((void**)&Wvh, g_Wvh);
    cudaGetSymbolAddress((void**)&Wvl, g_Wvl);
    cudaGetSymbolAddress((void**)&Qh, g_Qh);
    cudaGetSymbolAddress((void**)&Ql, g_Ql);
    cudaGetSymbolAddress((void**)&Kh, g_Kh);
    cudaGetSymbolAddress((void**)&Kl, g_Kl);
    cudaGetSymbolAddress((void**)&Vh, g_Vh);
    cudaGetSymbolAddress((void**)&Vl, g_Vl);
    cudaGetSymbolAddress((void**)&Ph, g_Ph);
    cudaGetSymbolAddress((void**)&Pl, g_Pl);
    cudaGetSymbolAddress((void**)&S, g_S);

    cudaFuncSetAttribute(gemm_sp, cudaFuncAttributeMaxDynamicSharedMemorySize, 131072);

    size_t nx = (size_t)N_TOK * DIM;
    split_f32<<<(unsigned)((nx + 255) / 256), 256>>>(X, Xh, Xl, nx);
    size_t nw = (size_t)DIM * DIM;
    unsigned gw = (unsigned)((nw + 255) / 256);
    split_f32<<<gw, 256>>>(Wq, Wqh, Wql, nw);
    split_f32<<<gw, 256>>>(Wk, Wkh, Wkl, nw);
    split_f32<<<gw, 256>>>(Wv, Wvh, Wvl, nw);

    dim3 blk(256, 1, 1);

    dim3 gqkv(DIM / 128, N_TOK / 128, 1);
    gemm_sp<<<gqkv, blk, 131072>>>(Xh, Xl, Wqh, Wql, (float*)0, Qh, Ql, N_TOK, DIM, DIM, 0, 1);
    gemm_sp<<<gqkv, blk, 131072>>>(Xh, Xl, Wkh, Wkl, (float*)0, Kh, Kl, N_TOK, DIM, DIM, 0, 1);
    gemm_sp<<<gqkv, blk, 131072>>>(Xh, Xl, Wvh, Wvl, (float*)0, Vh, Vl, N_TOK, DIM, DIM, 0, 1);

    dim3 gs(N_TOK / 128, N_TOK / 128, 1);
    gemm_sp<<<gs, blk, 131072>>>(Qh, Ql, Kh, Kl, S, (bf16*)0, (bf16*)0, N_TOK, N_TOK, DIM, 0, 0);

    softmax_rows<<<N_TOK, blk>>>(S, Ph, Pl);

    dim3 go(DIM / 128, N_TOK / 128, 1);
    gemm_sp<<<go, blk, 131072>>>(Ph, Pl, Vh, Vl, O, (bf16*)0, (bf16*)0, N_TOK, DIM, N_TOK, 1, 0);
}

// round 14
// speedup vs baseline: 3.0500x; 1.1284x over previous
#include <cuda_runtime.h>
#include <cuda_bf16.h>
#include <cstdint>
#include <cstddef>
#include <math.h>

#define N_TOK 8192
#define DIM   1024

typedef __nv_bfloat16 bf16;
typedef __nv_bfloat162 bf162;
typedef unsigned int u32;

// ---- scratch (static device arrays; no runtime allocation) ----
__device__ bf16 g_Xh[(size_t)N_TOK * DIM];
__device__ bf16 g_Xl[(size_t)N_TOK * DIM];
__device__ bf16 g_Wqh[DIM * DIM];
__device__ bf16 g_Wql[DIM * DIM];
__device__ bf16 g_Wkh[DIM * DIM];
__device__ bf16 g_Wkl[DIM * DIM];
__device__ bf16 g_Wvh[DIM * DIM];
__device__ bf16 g_Wvl[DIM * DIM];
__device__ bf16 g_Qh[(size_t)N_TOK * DIM];
__device__ bf16 g_Ql[(size_t)N_TOK * DIM];
__device__ bf16 g_Kh[(size_t)N_TOK * DIM];
__device__ bf16 g_Kl[(size_t)N_TOK * DIM];
__device__ bf16 g_Vth[(size_t)N_TOK * DIM];   // V^T: [DIM][N_TOK]
__device__ bf16 g_Vtl[(size_t)N_TOK * DIM];
__device__ float g_S[(size_t)N_TOK * N_TOK];
__device__ bf16 g_Ph[(size_t)N_TOK * N_TOK];
__device__ bf16 g_Pl[(size_t)N_TOK * N_TOK];

// ---- PTX helpers ----
__device__ __forceinline__ u32 smem_u32(const void* p) {
    return (u32)__cvta_generic_to_shared(p);
}
__device__ __forceinline__ void cp_async16(u32 dst, const void* src) {
    asm volatile("cp.async.cg.shared.global [%0], [%1], 16;" :: "r"(dst), "l"(src));
}
__device__ __forceinline__ void cp_commit() { asm volatile("cp.async.commit_group;"); }
__device__ __forceinline__ void cp_wait1()  { asm volatile("cp.async.wait_group 1;"); }

__device__ __forceinline__ void ldsm4(u32& r0, u32& r1, u32& r2, u32& r3, u32 addr) {
    asm volatile("ldmatrix.sync.aligned.m8n8.x4.shared.b16 {%0,%1,%2,%3}, [%4];"
                 : "=r"(r0), "=r"(r1), "=r"(r2), "=r"(r3) : "r"(addr));
}
__device__ __forceinline__ void mma16816(float* c, const u32* a, const u32* b) {
    asm volatile("mma.sync.aligned.m16n8k16.row.col.f32.bf16.bf16.f32 "
                 "{%0,%1,%2,%3}, {%4,%5,%6,%7}, {%8,%9}, {%0,%1,%2,%3};"
                 : "+f"(c[0]), "+f"(c[1]), "+f"(c[2]), "+f"(c[3])
                 : "r"(a[0]), "r"(a[1]), "r"(a[2]), "r"(a[3]), "r"(b[0]), "r"(b[1]));
}

// SW64-style swizzle for 64B rows: XOR bits[5:4] with bits[7:6]
__device__ __forceinline__ u32 swz64(u32 off) { return off ^ ((off >> 3) & 0x30u); }

// ---- fp32 -> (hi, lo) bf16 split ----
__global__ void __launch_bounds__(256) split_f32(const float* __restrict__ x,
                                                 bf16* __restrict__ h, bf16* __restrict__ l,
                                                 size_t n)
{
    size_t i = (size_t)blockIdx.x * blockDim.x + threadIdx.x;
    if (i < n) {
        float v = x[i];
        bf16 hi = __float2bfloat16(v);
        h[i] = hi;
        l[i] = __float2bfloat16(v - __bfloat162float(hi));
    }
}

// ---- stage loader: A [128][32] + B [128][32] bf16, hi+lo, 64B rows SW64 ----
// Slot layout: Ah @0, Al @8192, Bh @16384, Bl @24576 (32KB total)
__device__ __forceinline__ void load_stage(
    u32 slot,
    const bf16* Ah, const bf16* Al, const bf16* Bh, const bf16* Bl,
    int m0, int n0, int kt, int Kd, int tid)
{
    for (int c = tid; c < 512; c += 256) {
        int row = c >> 2;
        int cc = c & 3;
        u32 d = slot + swz64((u32)(row * 64 + cc * 16));
        size_t g = (size_t)(m0 + row) * Kd + (size_t)kt * 32 + cc * 8;
        cp_async16(d, Ah + g);
        cp_async16(d + 8192u, Al + g);
    }
    for (int c = tid; c < 512; c += 256) {
        int row = c >> 2;
        int cc = c & 3;
        u32 d = slot + 16384u + swz64((u32)(row * 64 + cc * 16));
        size_t g = (size_t)(n0 + row) * Kd + (size_t)kt * 32 + cc * 8;
        cp_async16(d, Bh + g);
        cp_async16(d + 8192u, Bl + g);
    }
}

// ============================================================================
// Split-bf16 GEMM (mma.sync): C[M,N] = A[M,K] * B[N,K]^T  (both K-major)
// 3 terms (AhBh + AhBl + AlBh). Tile 128x128, K-stage 32, 3-stage cp.async.
// 256 threads, warp grid 2x4 (warp tile 64x32), 2 CTAs/SM (96KB smem).
// ============================================================================
__global__ void __launch_bounds__(256, 2) gemm_sp3(
    const bf16* __restrict__ Ah, const bf16* __restrict__ Al,
    const bf16* __restrict__ Bh, const bf16* __restrict__ Bl,
    float* __restrict__ Cf, bf16* __restrict__ Ch, bf16* __restrict__ Cl,
    int Nd, int Kd, int splitout)
{
    extern __shared__ __align__(256) char smem[];
    const int tid  = threadIdx.x;
    const int lane = tid & 31;
    const int warp = tid >> 5;
    const int wm   = warp >> 2;   // 0..1
    const int wn   = warp & 3;    // 0..3
    const int m0   = blockIdx.y * 128;
    const int n0   = blockIdx.x * 128;
    const u32 sb   = smem_u32(smem);

    float acc[4][4][4];
#pragma unroll
    for (int i = 0; i < 4; i++) {
#pragma unroll
        for (int j = 0; j < 4; j++) {
#pragma unroll
            for (int k = 0; k < 4; k++) {
                acc[i][j][k] = 0.0f;
            }
        }
    }

    const int KT = Kd >> 5;   // K-stages of 32

    // prologue: stages 0 and 1
    load_stage(sb, Ah, Al, Bh, Bl, m0, n0, 0, Kd, tid);
    cp_commit();
    if (KT > 1) {
        load_stage(sb + 32768u, Ah, Al, Bh, Bl, m0, n0, 1, Kd, tid);
    }
    cp_commit();   // commit even if empty to keep group counting uniform

    for (int kt = 0; kt < KT; kt++) {
        cp_wait1();          // stage kt landed (<=1 newer group outstanding)
        __syncthreads();     // all warps done consuming stage kt-1

        if (kt + 2 < KT) {
            load_stage(sb + (u32)((kt + 2) % 3) * 32768u,
                       Ah, Al, Bh, Bl, m0, n0, kt + 2, Kd, tid);
        }
        cp_commit();

        const u32 sA = sb + (u32)(kt % 3) * 32768u;
        const u32 sB = sA + 16384u;

#pragma unroll
        for (int ks = 0; ks < 2; ks++) {
            u32 ah[4][4];
            u32 al[4][4];
            u32 bh[4][2];
            u32 bl[4][2];
#pragma unroll
            for (int mt = 0; mt < 4; mt++) {
                int row  = wm * 64 + mt * 16 + (lane & 15);
                int colb = ks * 32 + ((lane >> 4) << 4);
                u32 ad = sA + swz64((u32)(row * 64 + colb));
                ldsm4(ah[mt][0], ah[mt][1], ah[mt][2], ah[mt][3], ad);
                ldsm4(al[mt][0], al[mt][1], al[mt][2], al[mt][3], ad + 8192u);
            }
#pragma unroll
            for (int pr = 0; pr < 2; pr++) {
                int rowN = wn * 32 + pr * 16 + (lane & 7) + ((lane >> 4) << 3);
                int colb = ks * 32 + (((lane >> 3) & 1) << 4);
                u32 ad = sB + swz64((u32)(rowN * 64 + colb));
                ldsm4(bh[pr * 2][0], bh[pr * 2][1], bh[pr * 2 + 1][0], bh[pr * 2 + 1][1], ad);
                ldsm4(bl[pr * 2][0], bl[pr * 2][1], bl[pr * 2 + 1][0], bl[pr * 2 + 1][1], ad + 8192u);
            }
#pragma unroll
            for (int mt = 0; mt < 4; mt++) {
#pragma unroll
                for (int nt = 0; nt < 4; nt++) {
                    mma16816(acc[mt][nt], ah[mt], bh[nt]);
                }
            }
#pragma unroll
            for (int mt = 0; mt < 4; mt++) {
#pragma unroll
                for (int nt = 0; nt < 4; nt++) {
                    mma16816(acc[mt][nt], ah[mt], bl[nt]);
                }
            }
#pragma unroll
            for (int mt = 0; mt < 4; mt++) {
#pragma unroll
                for (int nt = 0; nt < 4; nt++) {
                    mma16816(acc[mt][nt], al[mt], bh[nt]);
                }
            }
        }
    }

    // ---- epilogue: direct register -> global (vectorized) ----
#pragma unroll
    for (int mt = 0; mt < 4; mt++) {
#pragma unroll
        for (int nt = 0; nt < 4; nt++) {
            int row = m0 + wm * 64 + mt * 16 + (lane >> 2);
            int col = n0 + wn * 32 + nt * 8 + (lane & 3) * 2;
            const float* c = acc[mt][nt];
            size_t i0 = (size_t)row * Nd + col;
            size_t i1 = (size_t)(row + 8) * Nd + col;
            if (splitout) {
                bf16 h0 = __float2bfloat16(c[0]);
                bf16 h1 = __float2bfloat16(c[1]);
                bf16 h2 = __float2bfloat16(c[2]);
                bf16 h3 = __float2bfloat16(c[3]);
                bf162 hp0;
                hp0.x = h0;
                hp0.y = h1;
                bf162 hp1;
                hp1.x = h2;
                hp1.y = h3;
                *(bf162*)(Ch + i0) = hp0;
                *(bf162*)(Ch + i1) = hp1;
                bf162 lp0;
                bf162 lp1;
                lp0.x = __float2bfloat16(c[0] - __bfloat162float(h0));
                lp0.y = __float2bfloat16(c[1] - __bfloat162float(h1));
                lp1.x = __float2bfloat16(c[2] - __bfloat162float(h2));
                lp1.y = __float2bfloat16(c[3] - __bfloat162float(h3));
                *(bf162*)(Cl + i0) = lp0;
                *(bf162*)(Cl + i1) = lp1;
            } else {
                *(float2*)(Cf + i0) = make_float2(c[0], c[1]);
                *(float2*)(Cf + i1) = make_float2(c[2], c[3]);
            }
        }
    }
}

// ---- row softmax: fp32 in, (hi, lo) bf16 out ----
__global__ void __launch_bounds__(256) softmax_rows(float* __restrict__ S,
                                                    bf16* __restrict__ Ph,
                                                    bf16* __restrict__ Pl)
{
    const int row = blockIdx.x;
    float4* p = (float4*)(S + (size_t)row * N_TOK);
    const int n4 = N_TOK / 4;
    const int tid = threadIdx.x;

    __shared__ float red[8];
    __shared__ float bcast;

    float m = -1e30f;
    for (int i = tid; i < n4; i += 256) {
        float4 v = p[i];
        m = fmaxf(m, fmaxf(fmaxf(v.x, v.y), fmaxf(v.z, v.w)));
    }
#pragma unroll
    for (int o = 16; o > 0; o >>= 1) {
        m = fmaxf(m, __shfl_xor_sync(0xffffffffu, m, o));
    }
    if ((tid & 31) == 0) {
        red[tid >> 5] = m;
    }
    __syncthreads();
    if (tid == 0) {
        float t = red[0];
#pragma unroll
        for (int i = 1; i < 8; i++) {
            t = fmaxf(t, red[i]);
        }
        bcast = t;
    }
    __syncthreads();
    const float rowmax = bcast;
    __syncthreads();

    float s = 0.0f;
    for (int i = tid; i < n4; i += 256) {
        float4 v = p[i];
        v.x = __expf(v.x - rowmax);
        v.y = __expf(v.y - rowmax);
        v.z = __expf(v.z - rowmax);
        v.w = __expf(v.w - rowmax);
        p[i] = v;
        s += v.x + v.y + v.z + v.w;
    }
#pragma unroll
    for (int o = 16; o > 0; o >>= 1) {
        s += __shfl_xor_sync(0xffffffffu, s, o);
    }
    if ((tid & 31) == 0) {
        red[tid >> 5] = s;
    }
    __syncthreads();
    if (tid == 0) {
        float t = 0.0f;
#pragma unroll
        for (int i = 0; i < 8; i++) {
            t += red[i];
        }
        bcast = 1.0f / t;
    }
    __syncthreads();
    const float inv = bcast;

    bf162* ph = (bf162*)(Ph + (size_t)row * N_TOK);
    bf162* pl = (bf162*)(Pl + (size_t)row * N_TOK);
    for (int i = tid; i < n4; i += 256) {
        float4 v = p[i];
        v.x *= inv;
        v.y *= inv;
        v.z *= inv;
        v.w *= inv;
        bf16 h0 = __float2bfloat16(v.x);
        bf16 h1 = __float2bfloat16(v.y);
        bf16 h2 = __float2bfloat16(v.z);
        bf16 h3 = __float2bfloat16(v.w);
        bf162 a;
        a.x = h0;
        a.y = h1;
        bf162 b;
        b.x = h2;
        b.y = h3;
        ph[2 * i] = a;
        ph[2 * i + 1] = b;
        bf162 cc;
        bf162 dd;
        cc.x = __float2bfloat16(v.x - __bfloat162float(h0));
        cc.y = __float2bfloat16(v.y - __bfloat162float(h1));
        dd.x = __float2bfloat16(v.z - __bfloat162float(h2));
        dd.y = __float2bfloat16(v.w - __bfloat162float(h3));
        pl[2 * i] = cc;
        pl[2 * i + 1] = dd;
    }
}

extern "C" void kernel_launch(void* const* d_in, const int* in_sizes, int n_in,
                              void* d_out, int out_size)
{
    const float* X  = (const float*)d_in[0];
    const float* Wq = (const float*)d_in[1];
    const float* Wk = (const float*)d_in[2];
    const float* Wv = (const float*)d_in[3];
    float* O = (float*)d_out;

    bf16* Xh;  bf16* Xl;
    bf16* Wqh; bf16* Wql;
    bf16* Wkh; bf16* Wkl;
    bf16* Wvh; bf16* Wvl;
    bf16* Qh;  bf16* Ql;
    bf16* Kh;  bf16* Kl;
    bf16* Vth; bf16* Vtl;
    bf16* Ph;  bf16* Pl;
    float* S;
    cudaGetSymbolAddress((void**)&Xh, g_Xh);
    cudaGetSymbolAddress((void**)&Xl, g_Xl);
    cudaGetSymbolAddress((void**)&Wqh, g_Wqh);
    cudaGetSymbolAddress((void**)&Wql, g_Wql);
    cudaGetSymbolAddress((void**)&Wkh, g_Wkh);
    cudaGetSymbolAddress((void**)&Wkl, g_Wkl);
    cudaGetSymbolAddress((void**)&Wvh, g_Wvh);
    cudaGetSymbolAddress((void**)&Wvl, g_Wvl);
    cudaGetSymbolAddress((void**)&Qh, g_Qh);
    cudaGetSymbolAddress((void**)&Ql, g_Ql);
    cudaGetSymbolAddress((void**)&Kh, g_Kh);
    cudaGetSymbolAddress((void**)&Kl, g_Kl);
    cudaGetSymbolAddress((void**)&Vth, g_Vth);
    cudaGetSymbolAddress((void**)&Vtl, g_Vtl);
    cudaGetSymbolAddress((void**)&Ph, g_Ph);
    cudaGetSymbolAddress((void**)&Pl, g_Pl);
    cudaGetSymbolAddress((void**)&S, g_S);

    cudaFuncSetAttribute(gemm_sp3, cudaFuncAttributeMaxDynamicSharedMemorySize, 98304);

    size_t nx = (size_t)N_TOK * DIM;
    split_f32<<<(unsigned)((nx + 255) / 256), 256>>>(X, Xh, Xl, nx);
    size_t nw = (size_t)DIM * DIM;
    unsigned gw = (unsigned)((nw + 255) / 256);
    split_f32<<<gw, 256>>>(Wq, Wqh, Wql, nw);
    split_f32<<<gw, 256>>>(Wk, Wkh, Wkl, nw);
    split_f32<<<gw, 256>>>(Wv, Wvh, Wvl, nw);

    dim3 blk(256, 1, 1);

    // Q = X Wq^T, K = X Wk^T : M=8192, N=1024, K=1024; split out
    dim3 gqk(DIM / 128, N_TOK / 128, 1);
    gemm_sp3<<<gqk, blk, 98304>>>(Xh, Xl, Wqh, Wql, (float*)0, Qh, Ql, DIM, DIM, 1);
    gemm_sp3<<<gqk, blk, 98304>>>(Xh, Xl, Wkh, Wkl, (float*)0, Kh, Kl, DIM, DIM, 1);

    // Vt = Wv X^T : M=1024, N=8192, K=1024; split out -> Vt[d][n]
    dim3 gvt(N_TOK / 128, DIM / 128, 1);
    gemm_sp3<<<gvt, blk, 98304>>>(Wvh, Wvl, Xh, Xl, (float*)0, Vth, Vtl, N_TOK, DIM, 1);

    // S = Q K^T : M=8192, N=8192, K=1024; fp32 out
    dim3 gs(N_TOK / 128, N_TOK / 128, 1);
    gemm_sp3<<<gs, blk, 98304>>>(Qh, Ql, Kh, Kl, S, (bf16*)0, (bf16*)0, N_TOK, DIM, 0);

    softmax_rows<<<N_TOK, blk>>>(S, Ph, Pl);

    // O = P Vt^T : M=8192, N=1024, K=8192; fp32 out
    dim3 go(DIM / 128, N_TOK / 128, 1);
    gemm_sp3<<<go, blk, 98304>>>(Ph, Pl, Vth, Vtl, O, (bf16*)0, (bf16*)0, DIM, N_TOK, 0);
}

// round 15
// speedup vs baseline: 3.2106x; 1.0527x over previous
#include <cuda_runtime.h>
#include <cuda_bf16.h>
#include <cstdint>
#include <cstddef>
#include <math.h>

#define N_TOK 8192
#define DIM   1024

typedef __nv_bfloat16 bf16;
typedef __nv_bfloat162 bf162;
typedef unsigned int u32;

// ---- scratch (static device arrays; no runtime allocation) ----
__device__ bf16 g_Xh[(size_t)N_TOK * DIM];
__device__ bf16 g_Xl[(size_t)N_TOK * DIM];
__device__ bf16 g_Wqh[DIM * DIM];
__device__ bf16 g_Wql[DIM * DIM];
__device__ bf16 g_Wkh[DIM * DIM];
__device__ bf16 g_Wkl[DIM * DIM];
__device__ bf16 g_Wvh[DIM * DIM];
__device__ bf16 g_Wvl[DIM * DIM];
__device__ bf16 g_Qh[(size_t)N_TOK * DIM];
__device__ bf16 g_Ql[(size_t)N_TOK * DIM];
__device__ bf16 g_Kh[(size_t)N_TOK * DIM];
__device__ bf16 g_Kl[(size_t)N_TOK * DIM];
__device__ bf16 g_Vth[(size_t)N_TOK * DIM];   // V^T: [DIM][N_TOK]
__device__ bf16 g_Vtl[(size_t)N_TOK * DIM];
__device__ bf16 g_Ph[(size_t)N_TOK * N_TOK];  // P~ = exp(S-40), hi
__device__ bf16 g_Pl[(size_t)N_TOK * N_TOK];  // P~ lo
__device__ float g_rowsum[N_TOK];

// ---- PTX helpers ----
__device__ __forceinline__ u32 smem_u32(const void* p) {
    return (u32)__cvta_generic_to_shared(p);
}
__device__ __forceinline__ void cp_async16(u32 dst, const void* src) {
    asm volatile("cp.async.cg.shared.global [%0], [%1], 16;" :: "r"(dst), "l"(src));
}
__device__ __forceinline__ void cp_commit() { asm volatile("cp.async.commit_group;"); }
__device__ __forceinline__ void cp_wait1()  { asm volatile("cp.async.wait_group 1;"); }

__device__ __forceinline__ void ldsm4(u32& r0, u32& r1, u32& r2, u32& r3, u32 addr) {
    asm volatile("ldmatrix.sync.aligned.m8n8.x4.shared.b16 {%0,%1,%2,%3}, [%4];"
                 : "=r"(r0), "=r"(r1), "=r"(r2), "=r"(r3) : "r"(addr));
}
__device__ __forceinline__ void mma16816(float* c, const u32* a, const u32* b) {
    asm volatile("mma.sync.aligned.m16n8k16.row.col.f32.bf16.bf16.f32 "
                 "{%0,%1,%2,%3}, {%4,%5,%6,%7}, {%8,%9}, {%0,%1,%2,%3};"
                 : "+f"(c[0]), "+f"(c[1]), "+f"(c[2]), "+f"(c[3])
                 : "r"(a[0]), "r"(a[1]), "r"(a[2]), "r"(a[3]), "r"(b[0]), "r"(b[1]));
}

// SW64-style swizzle for 64B rows: XOR bits[5:4] with bits[7:6]
__device__ __forceinline__ u32 swz64(u32 off) { return off ^ ((off >> 3) & 0x30u); }

// ---- fp32 -> (hi, lo) bf16 split ----
__global__ void __launch_bounds__(256) split_f32(const float* __restrict__ x,
                                                 bf16* __restrict__ h, bf16* __restrict__ l,
                                                 size_t n)
{
    size_t i = (size_t)blockIdx.x * blockDim.x + threadIdx.x;
    if (i < n) {
        float v = x[i];
        bf16 hi = __float2bfloat16(v);
        h[i] = hi;
        l[i] = __float2bfloat16(v - __bfloat162float(hi));
    }
}

__global__ void __launch_bounds__(256) zero_f32(float* __restrict__ p, int n)
{
    int i = blockIdx.x * blockDim.x + threadIdx.x;
    if (i < n) {
        p[i] = 0.0f;
    }
}

// ---- stage loader: A [128][32] + B [128][32] bf16, hi+lo, 64B rows SW64 ----
// Slot layout: Ah @0, Al @8192, Bh @16384, Bl @24576 (32KB total)
__device__ __forceinline__ void load_stage(
    u32 slot,
    const bf16* Ah, const bf16* Al, const bf16* Bh, const bf16* Bl,
    int m0, int n0, int kt, int Kd, int tid)
{
    for (int c = tid; c < 512; c += 256) {
        int row = c >> 2;
        int cc = c & 3;
        u32 d = slot + swz64((u32)(row * 64 + cc * 16));
        size_t g = (size_t)(m0 + row) * Kd + (size_t)kt * 32 + cc * 8;
        cp_async16(d, Ah + g);
        cp_async16(d + 8192u, Al + g);
    }
    for (int c = tid; c < 512; c += 256) {
        int row = c >> 2;
        int cc = c & 3;
        u32 d = slot + 16384u + swz64((u32)(row * 64 + cc * 16));
        size_t g = (size_t)(n0 + row) * Kd + (size_t)kt * 32 + cc * 8;
        cp_async16(d, Bh + g);
        cp_async16(d + 8192u, Bl + g);
    }
}

// ============================================================================
// Split-bf16 GEMM (mma.sync): C[M,N] = A[M,K] * B[N,K]^T  (both K-major)
// 3 terms (AhBh + AhBl + AlBh). Tile 128x128, K-stage 32, 3-stage cp.async.
// 256 threads, warp grid 2x4 (warp tile 64x32), 2 CTAs/SM (96KB smem).
// Epilogue modes:
//   0: Cf = c                       (fp32)
//   1: Ch/Cl = split(c)             (bf16 hi/lo)
//   2: Ch/Cl = split(exp(c - 40)); atomicAdd(rowsum[row], partial)
//   3: Cf = c * (1 / rowsum[row])   (deferred softmax normalization)
// ============================================================================
__global__ void __launch_bounds__(256, 2) gemm_sp3(
    const bf16* __restrict__ Ah, const bf16* __restrict__ Al,
    const bf16* __restrict__ Bh, const bf16* __restrict__ Bl,
    float* __restrict__ Cf, bf16* __restrict__ Ch, bf16* __restrict__ Cl,
    float* __restrict__ rowsum,
    int Nd, int Kd, int mode)
{
    extern __shared__ __align__(256) char smem[];
    const int tid  = threadIdx.x;
    const int lane = tid & 31;
    const int warp = tid >> 5;
    const int wm   = warp >> 2;   // 0..1
    const int wn   = warp & 3;    // 0..3
    const int m0   = blockIdx.y * 128;
    const int n0   = blockIdx.x * 128;
    const u32 sb   = smem_u32(smem);

    float acc[4][4][4];
#pragma unroll
    for (int i = 0; i < 4; i++) {
#pragma unroll
        for (int j = 0; j < 4; j++) {
#pragma unroll
            for (int k = 0; k < 4; k++) {
                acc[i][j][k] = 0.0f;
            }
        }
    }

    const int KT = Kd >> 5;   // K-stages of 32

    // prologue: stages 0 and 1
    load_stage(sb, Ah, Al, Bh, Bl, m0, n0, 0, Kd, tid);
    cp_commit();
    if (KT > 1) {
        load_stage(sb + 32768u, Ah, Al, Bh, Bl, m0, n0, 1, Kd, tid);
    }
    cp_commit();   // commit even if empty to keep group counting uniform

    for (int kt = 0; kt < KT; kt++) {
        cp_wait1();          // stage kt landed (<=1 newer group outstanding)
        __syncthreads();     // all warps done consuming stage kt-1

        if (kt + 2 < KT) {
            load_stage(sb + (u32)((kt + 2) % 3) * 32768u,
                       Ah, Al, Bh, Bl, m0, n0, kt + 2, Kd, tid);
        }
        cp_commit();

        const u32 sA = sb + (u32)(kt % 3) * 32768u;
        const u32 sB = sA + 16384u;

#pragma unroll
        for (int ks = 0; ks < 2; ks++) {
            u32 ah[4][4];
            u32 al[4][4];
            u32 bh[4][2];
            u32 bl[4][2];
#pragma unroll
            for (int mt = 0; mt < 4; mt++) {
                int row  = wm * 64 + mt * 16 + (lane & 15);
                int colb = ks * 32 + ((lane >> 4) << 4);
                u32 ad = sA + swz64((u32)(row * 64 + colb));
                ldsm4(ah[mt][0], ah[mt][1], ah[mt][2], ah[mt][3], ad);
                ldsm4(al[mt][0], al[mt][1], al[mt][2], al[mt][3], ad + 8192u);
            }
#pragma unroll
            for (int pr = 0; pr < 2; pr++) {
                int rowN = wn * 32 + pr * 16 + (lane & 7) + ((lane >> 4) << 3);
                int colb = ks * 32 + (((lane >> 3) & 1) << 4);
                u32 ad = sB + swz64((u32)(rowN * 64 + colb));
                ldsm4(bh[pr * 2][0], bh[pr * 2][1], bh[pr * 2 + 1][0], bh[pr * 2 + 1][1], ad);
                ldsm4(bl[pr * 2][0], bl[pr * 2][1], bl[pr * 2 + 1][0], bl[pr * 2 + 1][1], ad + 8192u);
            }
#pragma unroll
            for (int mt = 0; mt < 4; mt++) {
#pragma unroll
                for (int nt = 0; nt < 4; nt++) {
                    mma16816(acc[mt][nt], ah[mt], bh[nt]);
                }
            }
#pragma unroll
            for (int mt = 0; mt < 4; mt++) {
#pragma unroll
                for (int nt = 0; nt < 4; nt++) {
                    mma16816(acc[mt][nt], ah[mt], bl[nt]);
                }
            }
#pragma unroll
            for (int mt = 0; mt < 4; mt++) {
#pragma unroll
                for (int nt = 0; nt < 4; nt++) {
                    mma16816(acc[mt][nt], al[mt], bh[nt]);
                }
            }
        }
    }

    // ---- epilogue ----
    if (mode == 2) {
        // exp(c - 40) -> split bf16 P~, accumulate row sums
#pragma unroll
        for (int mt = 0; mt < 4; mt++) {
            int r0 = m0 + wm * 64 + mt * 16 + (lane >> 2);
            float s0 = 0.0f;
            float s1 = 0.0f;
#pragma unroll
            for (int nt = 0; nt < 4; nt++) {
                float* c = acc[mt][nt];
                float e0 = __expf(c[0] - 40.0f);
                float e1 = __expf(c[1] - 40.0f);
                float e2 = __expf(c[2] - 40.0f);
                float e3 = __expf(c[3] - 40.0f);
                s0 += e0 + e1;
                s1 += e2 + e3;
                int col = n0 + wn * 32 + nt * 8 + (lane & 3) * 2;
                size_t i0 = (size_t)r0 * Nd + col;
                size_t i1 = (size_t)(r0 + 8) * Nd + col;
                bf16 h0 = __float2bfloat16(e0);
                bf16 h1 = __float2bfloat16(e1);
                bf16 h2 = __float2bfloat16(e2);
                bf16 h3 = __float2bfloat16(e3);
                bf162 hp0;
                hp0.x = h0;
                hp0.y = h1;
                bf162 hp1;
                hp1.x = h2;
                hp1.y = h3;
                *(bf162*)(Ch + i0) = hp0;
                *(bf162*)(Ch + i1) = hp1;
                bf162 lp0;
                bf162 lp1;
                lp0.x = __float2bfloat16(e0 - __bfloat162float(h0));
                lp0.y = __float2bfloat16(e1 - __bfloat162float(h1));
                lp1.x = __float2bfloat16(e2 - __bfloat162float(h2));
                lp1.y = __float2bfloat16(e3 - __bfloat162float(h3));
                *(bf162*)(Cl + i0) = lp0;
                *(bf162*)(Cl + i1) = lp1;
            }
            // quad reduce (lanes sharing the same row)
            s0 += __shfl_xor_sync(0xffffffffu, s0, 1);
            s0 += __shfl_xor_sync(0xffffffffu, s0, 2);
            s1 += __shfl_xor_sync(0xffffffffu, s1, 1);
            s1 += __shfl_xor_sync(0xffffffffu, s1, 2);
            if ((lane & 3) == 0) {
                atomicAdd(rowsum + r0, s0);
                atomicAdd(rowsum + r0 + 8, s1);
            }
        }
    } else if (mode == 3) {
        // deferred softmax normalization: scale rows by 1/rowsum
#pragma unroll
        for (int mt = 0; mt < 4; mt++) {
            int r0 = m0 + wm * 64 + mt * 16 + (lane >> 2);
            float sc0 = 1.0f / __ldg(rowsum + r0);
            float sc1 = 1.0f / __ldg(rowsum + r0 + 8);
#pragma unroll
            for (int nt = 0; nt < 4; nt++) {
                int col = n0 + wn * 32 + nt * 8 + (lane & 3) * 2;
                const float* c = acc[mt][nt];
                size_t i0 = (size_t)r0 * Nd + col;
                size_t i1 = (size_t)(r0 + 8) * Nd + col;
                *(float2*)(Cf + i0) = make_float2(c[0] * sc0, c[1] * sc0);
                *(float2*)(Cf + i1) = make_float2(c[2] * sc1, c[3] * sc1);
            }
        }
    } else if (mode == 1) {
#pragma unroll
        for (int mt = 0; mt < 4; mt++) {
#pragma unroll
            for (int nt = 0; nt < 4; nt++) {
                int row = m0 + wm * 64 + mt * 16 + (lane >> 2);
                int col = n0 + wn * 32 + nt * 8 + (lane & 3) * 2;
                const float* c = acc[mt][nt];
                size_t i0 = (size_t)row * Nd + col;
                size_t i1 = (size_t)(row + 8) * Nd + col;
                bf16 h0 = __float2bfloat16(c[0]);
                bf16 h1 = __float2bfloat16(c[1]);
                bf16 h2 = __float2bfloat16(c[2]);
                bf16 h3 = __float2bfloat16(c[3]);
                bf162 hp0;
                hp0.x = h0;
                hp0.y = h1;
                bf162 hp1;
                hp1.x = h2;
                hp1.y = h3;
                *(bf162*)(Ch + i0) = hp0;
                *(bf162*)(Ch + i1) = hp1;
                bf162 lp0;
                bf162 lp1;
                lp0.x = __float2bfloat16(c[0] - __bfloat162float(h0));
                lp0.y = __float2bfloat16(c[1] - __bfloat162float(h1));
                lp1.x = __float2bfloat16(c[2] - __bfloat162float(h2));
                lp1.y = __float2bfloat16(c[3] - __bfloat162float(h3));
                *(bf162*)(Cl + i0) = lp0;
                *(bf162*)(Cl + i1) = lp1;
            }
        }
    } else {
#pragma unroll
        for (int mt = 0; mt < 4; mt++) {
#pragma unroll
            for (int nt = 0; nt < 4; nt++) {
                int row = m0 + wm * 64 + mt * 16 + (lane >> 2);
                int col = n0 + wn * 32 + nt * 8 + (lane & 3) * 2;
                const float* c = acc[mt][nt];
                size_t i0 = (size_t)row * Nd + col;
                size_t i1 = (size_t)(row + 8) * Nd + col;
                *(float2*)(Cf + i0) = make_float2(c[0], c[1]);
                *(float2*)(Cf + i1) = make_float2(c[2], c[3]);
            }
        }
    }
}

extern "C" void kernel_launch(void* const* d_in, const int* in_sizes, int n_in,
                              void* d_out, int out_size)
{
    const float* X  = (const float*)d_in[0];
    const float* Wq = (const float*)d_in[1];
    const float* Wk = (const float*)d_in[2];
    const float* Wv = (const float*)d_in[3];
    float* O = (float*)d_out;

    bf16* Xh;  bf16* Xl;
    bf16* Wqh; bf16* Wql;
    bf16* Wkh; bf16* Wkl;
    bf16* Wvh; bf16* Wvl;
    bf16* Qh;  bf16* Ql;
    bf16* Kh;  bf16* Kl;
    bf16* Vth; bf16* Vtl;
    bf16* Ph;  bf16* Pl;
    float* rowsum;
    cudaGetSymbolAddress((void**)&Xh, g_Xh);
    cudaGetSymbolAddress((void**)&Xl, g_Xl);
    cudaGetSymbolAddress((void**)&Wqh, g_Wqh);
    cudaGetSymbolAddress((void**)&Wql, g_Wql);
    cudaGetSymbolAddress((void**)&Wkh, g_Wkh);
    cudaGetSymbolAddress((void**)&Wkl, g_Wkl);
    cudaGetSymbolAddress((void**)&Wvh, g_Wvh);
    cudaGetSymbolAddress((void**)&Wvl, g_Wvl);
    cudaGetSymbolAddress((void**)&Qh, g_Qh);
    cudaGetSymbolAddress((void**)&Ql, g_Ql);
    cudaGetSymbolAddress((void**)&Kh, g_Kh);
    cudaGetSymbolAddress((void**)&Kl, g_Kl);
    cudaGetSymbolAddress((void**)&Vth, g_Vth);
    cudaGetSymbolAddress((void**)&Vtl, g_Vtl);
    cudaGetSymbolAddress((void**)&Ph, g_Ph);
    cudaGetSymbolAddress((void**)&Pl, g_Pl);
    cudaGetSymbolAddress((void**)&rowsum, g_rowsum);

    cudaFuncSetAttribute(gemm_sp3, cudaFuncAttributeMaxDynamicSharedMemorySize, 98304);

    size_t nx = (size_t)N_TOK * DIM;
    split_f32<<<(unsigned)((nx + 255) / 256), 256>>>(X, Xh, Xl, nx);
    size_t nw = (size_t)DIM * DIM;
    unsigned gw = (unsigned)((nw + 255) / 256);
    split_f32<<<gw, 256>>>(Wq, Wqh, Wql, nw);
    split_f32<<<gw, 256>>>(Wk, Wkh, Wkl, nw);
    split_f32<<<gw, 256>>>(Wv, Wvh, Wvl, nw);
    zero_f32<<<N_TOK / 256, 256>>>(rowsum, N_TOK);

    dim3 blk(256, 1, 1);

    // Q = X Wq^T, K = X Wk^T : M=8192, N=1024, K=1024; split out
    dim3 gqk(DIM / 128, N_TOK / 128, 1);
    gemm_sp3<<<gqk, blk, 98304>>>(Xh, Xl, Wqh, Wql, (float*)0, Qh, Ql, (float*)0, DIM, DIM, 1);
    gemm_sp3<<<gqk, blk, 98304>>>(Xh, Xl, Wkh, Wkl, (float*)0, Kh, Kl, (float*)0, DIM, DIM, 1);

    // Vt = Wv X^T : M=1024, N=8192, K=1024; split out -> Vt[d][n]
    dim3 gvt(N_TOK / 128, DIM / 128, 1);
    gemm_sp3<<<gvt, blk, 98304>>>(Wvh, Wvl, Xh, Xl, (float*)0, Vth, Vtl, (float*)0, N_TOK, DIM, 1);

    // P~ = exp(Q K^T - 40) : M=8192, N=8192, K=1024; split out + rowsum
    dim3 gs(N_TOK / 128, N_TOK / 128, 1);
    gemm_sp3<<<gs, blk, 98304>>>(Qh, Ql, Kh, Kl, (float*)0, Ph, Pl, rowsum, N_TOK, DIM, 2);

    // O = (P~ Vt^T) / rowsum : M=8192, N=1024, K=8192; scaled fp32 out
    dim3 go(DIM / 128, N_TOK / 128, 1);
    gemm_sp3<<<go, blk, 98304>>>(Ph, Pl, Vth, Vtl, O, (bf16*)0, (bf16*)0, rowsum, DIM, N_TOK, 3);
}

// round 16
// speedup vs baseline: 3.2878x; 1.0240x over previous
#include <cuda_runtime.h>
#include <cuda_bf16.h>
#include <cstdint>
#include <cstddef>
#include <math.h>

#define N_TOK 8192
#define DIM   1024

typedef __nv_bfloat16 bf16;
typedef __nv_bfloat162 bf162;
typedef unsigned int u32;

// ---- scratch (static device arrays; no runtime allocation) ----
__device__ bf16 g_Xh[(size_t)N_TOK * DIM];
__device__ bf16 g_Xl[(size_t)N_TOK * DIM];
__device__ bf16 g_Wqh[DIM * DIM];
__device__ bf16 g_Wql[DIM * DIM];
__device__ bf16 g_Wkh[DIM * DIM];
__device__ bf16 g_Wkl[DIM * DIM];
__device__ bf16 g_Wvh[DIM * DIM];
__device__ bf16 g_Wvl[DIM * DIM];
__device__ bf16 g_Qh[(size_t)N_TOK * DIM];
__device__ bf16 g_Ql[(size_t)N_TOK * DIM];
__device__ bf16 g_Kh[(size_t)N_TOK * DIM];
__device__ bf16 g_Kl[(size_t)N_TOK * DIM];
__device__ bf16 g_Vth[(size_t)N_TOK * DIM];   // V^T: [DIM][N_TOK]
__device__ bf16 g_Vtl[(size_t)N_TOK * DIM];
__device__ bf16 g_Ph[(size_t)N_TOK * N_TOK];  // P~ = exp(S-40), hi
__device__ bf16 g_Pl[(size_t)N_TOK * N_TOK];  // P~ lo
__device__ float g_rowsum[N_TOK];

// ---- PTX helpers ----
__device__ __forceinline__ u32 smem_u32(const void* p) {
    return (u32)__cvta_generic_to_shared(p);
}
__device__ __forceinline__ void cp_async16(u32 dst, const void* src) {
    asm volatile("cp.async.cg.shared.global [%0], [%1], 16;" :: "r"(dst), "l"(src));
}
__device__ __forceinline__ void cp_commit() { asm volatile("cp.async.commit_group;"); }
__device__ __forceinline__ void cp_wait1()  { asm volatile("cp.async.wait_group 1;"); }

__device__ __forceinline__ void ldsm4(u32& r0, u32& r1, u32& r2, u32& r3, u32 addr) {
    asm volatile("ldmatrix.sync.aligned.m8n8.x4.shared.b16 {%0,%1,%2,%3}, [%4];"
                 : "=r"(r0), "=r"(r1), "=r"(r2), "=r"(r3) : "r"(addr));
}
__device__ __forceinline__ void mma16816(float* c, const u32* a, const u32* b) {
    asm volatile("mma.sync.aligned.m16n8k16.row.col.f32.bf16.bf16.f32 "
                 "{%0,%1,%2,%3}, {%4,%5,%6,%7}, {%8,%9}, {%0,%1,%2,%3};"
                 : "+f"(c[0]), "+f"(c[1]), "+f"(c[2]), "+f"(c[3])
                 : "r"(a[0]), "r"(a[1]), "r"(a[2]), "r"(a[3]), "r"(b[0]), "r"(b[1]));
}

// SW64-style swizzle for 64B rows: XOR bits[5:4] with bits[7:6]
__device__ __forceinline__ u32 swz64(u32 off) { return off ^ ((off >> 3) & 0x30u); }

// ---- fp32 -> (hi, lo) bf16 split ----
__global__ void __launch_bounds__(256) split_f32(const float* __restrict__ x,
                                                 bf16* __restrict__ h, bf16* __restrict__ l,
                                                 size_t n)
{
    size_t i = (size_t)blockIdx.x * blockDim.x + threadIdx.x;
    if (i < n) {
        float v = x[i];
        bf16 hi = __float2bfloat16(v);
        h[i] = hi;
        l[i] = __float2bfloat16(v - __bfloat162float(hi));
    }
}

__global__ void __launch_bounds__(256) zero_f32(float* __restrict__ p, int n)
{
    int i = blockIdx.x * blockDim.x + threadIdx.x;
    if (i < n) {
        p[i] = 0.0f;
    }
}

// ---- stage loader: A [128][32] + B [128][32] bf16, hi+lo, 64B rows SW64 ----
// Slot layout: Ah @0, Al @8192, Bh @16384, Bl @24576 (32KB total)
__device__ __forceinline__ void load_stage(
    u32 slot,
    const bf16* Ah, const bf16* Al, const bf16* Bh, const bf16* Bl,
    int m0, int n0, int kt, int Kd, int tid)
{
    for (int c = tid; c < 512; c += 256) {
        int row = c >> 2;
        int cc = c & 3;
        u32 d = slot + swz64((u32)(row * 64 + cc * 16));
        size_t g = (size_t)(m0 + row) * Kd + (size_t)kt * 32 + cc * 8;
        cp_async16(d, Ah + g);
        cp_async16(d + 8192u, Al + g);
    }
    for (int c = tid; c < 512; c += 256) {
        int row = c >> 2;
        int cc = c & 3;
        u32 d = slot + 16384u + swz64((u32)(row * 64 + cc * 16));
        size_t g = (size_t)(n0 + row) * Kd + (size_t)kt * 32 + cc * 8;
        cp_async16(d, Bh + g);
        cp_async16(d + 8192u, Bl + g);
    }
}

// ---- GEMM mainloop core: acc += A * B^T over K (3 split terms) ----
// Staged fragment loads (hh -> hl -> lh) to shrink peak register pressure.
__device__ __forceinline__ void gemm_core(
    const bf16* Ah, const bf16* Al, const bf16* Bh, const bf16* Bl,
    int m0, int n0, int Kd, int tid, int lane, int wm, int wn,
    u32 sb, float (*acc)[4][4])
{
    const int KT = Kd >> 5;   // K-stages of 32

    load_stage(sb, Ah, Al, Bh, Bl, m0, n0, 0, Kd, tid);
    cp_commit();
    if (KT > 1) {
        load_stage(sb + 32768u, Ah, Al, Bh, Bl, m0, n0, 1, Kd, tid);
    }
    cp_commit();

    for (int kt = 0; kt < KT; kt++) {
        cp_wait1();
        __syncthreads();

        if (kt + 2 < KT) {
            load_stage(sb + (u32)((kt + 2) % 3) * 32768u,
                       Ah, Al, Bh, Bl, m0, n0, kt + 2, Kd, tid);
        }
        cp_commit();

        const u32 sA = sb + (u32)(kt % 3) * 32768u;
        const u32 sB = sA + 16384u;

#pragma unroll
        for (int ks = 0; ks < 2; ks++) {
            // --- hh pass ---
            u32 ah[4][4];
            u32 bh[4][2];
#pragma unroll
            for (int mt = 0; mt < 4; mt++) {
                int row  = wm * 64 + mt * 16 + (lane & 15);
                int colb = ks * 32 + ((lane >> 4) << 4);
                u32 ad = sA + swz64((u32)(row * 64 + colb));
                ldsm4(ah[mt][0], ah[mt][1], ah[mt][2], ah[mt][3], ad);
            }
#pragma unroll
            for (int pr = 0; pr < 2; pr++) {
                int rowN = wn * 32 + pr * 16 + (lane & 7) + ((lane >> 4) << 3);
                int colb = ks * 32 + (((lane >> 3) & 1) << 4);
                u32 ad = sB + swz64((u32)(rowN * 64 + colb));
                ldsm4(bh[pr * 2][0], bh[pr * 2][1], bh[pr * 2 + 1][0], bh[pr * 2 + 1][1], ad);
            }
#pragma unroll
            for (int mt = 0; mt < 4; mt++) {
#pragma unroll
                for (int nt = 0; nt < 4; nt++) {
                    mma16816(acc[mt][nt], ah[mt], bh[nt]);
                }
            }
            // --- hl pass (ah still live, load bl) ---
            u32 bl[4][2];
#pragma unroll
            for (int pr = 0; pr < 2; pr++) {
                int rowN = wn * 32 + pr * 16 + (lane & 7) + ((lane >> 4) << 3);
                int colb = ks * 32 + (((lane >> 3) & 1) << 4);
                u32 ad = sB + 8192u + swz64((u32)(rowN * 64 + colb));
                ldsm4(bl[pr * 2][0], bl[pr * 2][1], bl[pr * 2 + 1][0], bl[pr * 2 + 1][1], ad);
            }
#pragma unroll
            for (int mt = 0; mt < 4; mt++) {
#pragma unroll
                for (int nt = 0; nt < 4; nt++) {
                    mma16816(acc[mt][nt], ah[mt], bl[nt]);
                }
            }
            // --- lh pass (ah dead, load al) ---
            u32 al[4][4];
#pragma unroll
            for (int mt = 0; mt < 4; mt++) {
                int row  = wm * 64 + mt * 16 + (lane & 15);
                int colb = ks * 32 + ((lane >> 4) << 4);
                u32 ad = sA + 8192u + swz64((u32)(row * 64 + colb));
                ldsm4(al[mt][0], al[mt][1], al[mt][2], al[mt][3], ad);
            }
#pragma unroll
            for (int mt = 0; mt < 4; mt++) {
#pragma unroll
                for (int nt = 0; nt < 4; nt++) {
                    mma16816(acc[mt][nt], al[mt], bh[nt]);
                }
            }
        }
    }
}

// ---- split-store epilogue (mode 1) ----
__device__ __forceinline__ void epi_split(
    float (*acc)[4][4], bf16* Ch, bf16* Cl,
    int m0, int n0, int Nd, int lane, int wm, int wn)
{
#pragma unroll
    for (int mt = 0; mt < 4; mt++) {
#pragma unroll
        for (int nt = 0; nt < 4; nt++) {
            int row = m0 + wm * 64 + mt * 16 + (lane >> 2);
            int col = n0 + wn * 32 + nt * 8 + (lane & 3) * 2;
            const float* c = acc[mt][nt];
            size_t i0 = (size_t)row * Nd + col;
            size_t i1 = (size_t)(row + 8) * Nd + col;
            bf16 h0 = __float2bfloat16(c[0]);
            bf16 h1 = __float2bfloat16(c[1]);
            bf16 h2 = __float2bfloat16(c[2]);
            bf16 h3 = __float2bfloat16(c[3]);
            bf162 hp0;
            hp0.x = h0;
            hp0.y = h1;
            bf162 hp1;
            hp1.x = h2;
            hp1.y = h3;
            *(bf162*)(Ch + i0) = hp0;
            *(bf162*)(Ch + i1) = hp1;
            bf162 lp0;
            bf162 lp1;
            lp0.x = __float2bfloat16(c[0] - __bfloat162float(h0));
            lp0.y = __float2bfloat16(c[1] - __bfloat162float(h1));
            lp1.x = __float2bfloat16(c[2] - __bfloat162float(h2));
            lp1.y = __float2bfloat16(c[3] - __bfloat162float(h3));
            *(bf162*)(Cl + i0) = lp0;
            *(bf162*)(Cl + i1) = lp1;
        }
    }
}

// ============================================================================
// Fused QKV projections in one launch. grid (8, 64, 3):
//   z=0: Q  = X Wq^T   (m0 = by*128, n0 = bx*128, Nd=1024)
//   z=1: K  = X Wk^T   (same shape)
//   z=2: Vt = Wv X^T   (m0 = bx*128, n0 = by*128, Nd=8192)
// ============================================================================
__global__ void __launch_bounds__(256, 2) qkv_fused(
    const bf16* __restrict__ Xh, const bf16* __restrict__ Xl,
    const bf16* __restrict__ Wqh, const bf16* __restrict__ Wql,
    const bf16* __restrict__ Wkh, const bf16* __restrict__ Wkl,
    const bf16* __restrict__ Wvh, const bf16* __restrict__ Wvl,
    bf16* __restrict__ Qh, bf16* __restrict__ Ql,
    bf16* __restrict__ Kh, bf16* __restrict__ Kl,
    bf16* __restrict__ Vth, bf16* __restrict__ Vtl)
{
    extern __shared__ __align__(256) char smem[];
    const int tid  = threadIdx.x;
    const int lane = tid & 31;
    const int warp = tid >> 5;
    const int wm   = warp >> 2;
    const int wn   = warp & 3;
    const u32 sb   = smem_u32(smem);
    const int z    = blockIdx.z;

    const bf16* Ah;
    const bf16* Al;
    const bf16* Bh;
    const bf16* Bl;
    bf16* Ch;
    bf16* Cl;
    int m0;
    int n0;
    int Nd;
    if (z == 0) {
        Ah = Xh; Al = Xl; Bh = Wqh; Bl = Wql; Ch = Qh; Cl = Ql;
        m0 = blockIdx.y * 128;
        n0 = blockIdx.x * 128;
        Nd = DIM;
    } else if (z == 1) {
        Ah = Xh; Al = Xl; Bh = Wkh; Bl = Wkl; Ch = Kh; Cl = Kl;
        m0 = blockIdx.y * 128;
        n0 = blockIdx.x * 128;
        Nd = DIM;
    } else {
        Ah = Wvh; Al = Wvl; Bh = Xh; Bl = Xl; Ch = Vth; Cl = Vtl;
        m0 = blockIdx.x * 128;
        n0 = blockIdx.y * 128;
        Nd = N_TOK;
    }

    float acc[4][4][4];
#pragma unroll
    for (int i = 0; i < 4; i++) {
#pragma unroll
        for (int j = 0; j < 4; j++) {
#pragma unroll
            for (int k = 0; k < 4; k++) {
                acc[i][j][k] = 0.0f;
            }
        }
    }

    gemm_core(Ah, Al, Bh, Bl, m0, n0, DIM, tid, lane, wm, wn, sb, acc);
    epi_split(acc, Ch, Cl, m0, n0, Nd, lane, wm, wn);
}

// ============================================================================
// Split-bf16 GEMM, modes:
//   2: Ch/Cl = split(exp(c - 40)); atomicAdd(rowsum[row], partial)
//   3: Cf = c * (1 / rowsum[row])
// ============================================================================
__global__ void __launch_bounds__(256, 2) gemm_sp3(
    const bf16* __restrict__ Ah, const bf16* __restrict__ Al,
    const bf16* __restrict__ Bh, const bf16* __restrict__ Bl,
    float* __restrict__ Cf, bf16* __restrict__ Ch, bf16* __restrict__ Cl,
    float* __restrict__ rowsum,
    int Nd, int Kd, int mode)
{
    extern __shared__ __align__(256) char smem[];
    const int tid  = threadIdx.x;
    const int lane = tid & 31;
    const int warp = tid >> 5;
    const int wm   = warp >> 2;
    const int wn   = warp & 3;
    const int m0   = blockIdx.y * 128;
    const int n0   = blockIdx.x * 128;
    const u32 sb   = smem_u32(smem);

    float acc[4][4][4];
#pragma unroll
    for (int i = 0; i < 4; i++) {
#pragma unroll
        for (int j = 0; j < 4; j++) {
#pragma unroll
            for (int k = 0; k < 4; k++) {
                acc[i][j][k] = 0.0f;
            }
        }
    }

    gemm_core(Ah, Al, Bh, Bl, m0, n0, Kd, tid, lane, wm, wn, sb, acc);

    if (mode == 2) {
        // exp(c - 40) -> split bf16 P~, accumulate row sums
#pragma unroll
        for (int mt = 0; mt < 4; mt++) {
            int r0 = m0 + wm * 64 + mt * 16 + (lane >> 2);
            float s0 = 0.0f;
            float s1 = 0.0f;
#pragma unroll
            for (int nt = 0; nt < 4; nt++) {
                float* c = acc[mt][nt];
                float e0 = __expf(c[0] - 40.0f);
                float e1 = __expf(c[1] - 40.0f);
                float e2 = __expf(c[2] - 40.0f);
                float e3 = __expf(c[3] - 40.0f);
                s0 += e0 + e1;
                s1 += e2 + e3;
                int col = n0 + wn * 32 + nt * 8 + (lane & 3) * 2;
                size_t i0 = (size_t)r0 * Nd + col;
                size_t i1 = (size_t)(r0 + 8) * Nd + col;
                bf16 h0 = __float2bfloat16(e0);
                bf16 h1 = __float2bfloat16(e1);
                bf16 h2 = __float2bfloat16(e2);
                bf16 h3 = __float2bfloat16(e3);
                bf162 hp0;
                hp0.x = h0;
                hp0.y = h1;
                bf162 hp1;
                hp1.x = h2;
                hp1.y = h3;
                *(bf162*)(Ch + i0) = hp0;
                *(bf162*)(Ch + i1) = hp1;
                bf162 lp0;
                bf162 lp1;
                lp0.x = __float2bfloat16(e0 - __bfloat162float(h0));
                lp0.y = __float2bfloat16(e1 - __bfloat162float(h1));
                lp1.x = __float2bfloat16(e2 - __bfloat162float(h2));
                lp1.y = __float2bfloat16(e3 - __bfloat162float(h3));
                *(bf162*)(Cl + i0) = lp0;
                *(bf162*)(Cl + i1) = lp1;
            }
            s0 += __shfl_xor_sync(0xffffffffu, s0, 1);
            s0 += __shfl_xor_sync(0xffffffffu, s0, 2);
            s1 += __shfl_xor_sync(0xffffffffu, s1, 1);
            s1 += __shfl_xor_sync(0xffffffffu, s1, 2);
            if ((lane & 3) == 0) {
                atomicAdd(rowsum + r0, s0);
                atomicAdd(rowsum + r0 + 8, s1);
            }
        }
    } else {
        // mode 3: deferred softmax normalization
#pragma unroll
        for (int mt = 0; mt < 4; mt++) {
            int r0 = m0 + wm * 64 + mt * 16 + (lane >> 2);
            float sc0 = 1.0f / __ldg(rowsum + r0);
            float sc1 = 1.0f / __ldg(rowsum + r0 + 8);
#pragma unroll
            for (int nt = 0; nt < 4; nt++) {
                int col = n0 + wn * 32 + nt * 8 + (lane & 3) * 2;
                const float* c = acc[mt][nt];
                size_t i0 = (size_t)r0 * Nd + col;
                size_t i1 = (size_t)(r0 + 8) * Nd + col;
                *(float2*)(Cf + i0) = make_float2(c[0] * sc0, c[1] * sc0);
                *(float2*)(Cf + i1) = make_float2(c[2] * sc1, c[3] * sc1);
            }
        }
    }
}

extern "C" void kernel_launch(void* const* d_in, const int* in_sizes, int n_in,
                              void* d_out, int out_size)
{
    const float* X  = (const float*)d_in[0];
    const float* Wq = (const float*)d_in[1];
    const float* Wk = (const float*)d_in[2];
    const float* Wv = (const float*)d_in[3];
    float* O = (float*)d_out;

    bf16* Xh;  bf16* Xl;
    bf16* Wqh; bf16* Wql;
    bf16* Wkh; bf16* Wkl;
    bf16* Wvh; bf16* Wvl;
    bf16* Qh;  bf16* Ql;
    bf16* Kh;  bf16* Kl;
    bf16* Vth; bf16* Vtl;
    bf16* Ph;  bf16* Pl;
    float* rowsum;
    cudaGetSymbolAddress((void**)&Xh, g_Xh);
    cudaGetSymbolAddress((void**)&Xl, g_Xl);
    cudaGetSymbolAddress((void**)&Wqh, g_Wqh);
    cudaGetSymbolAddress((void**)&Wql, g_Wql);
    cudaGetSymbolAddress((void**)&Wkh, g_Wkh);
    cudaGetSymbolAddress((void**)&Wkl, g_Wkl);
    cudaGetSymbolAddress((void**)&Wvh, g_Wvh);
    cudaGetSymbolAddress((void**)&Wvl, g_Wvl);
    cudaGetSymbolAddress((void**)&Qh, g_Qh);
    cudaGetSymbolAddress((void**)&Ql, g_Ql);
    cudaGetSymbolAddress((void**)&Kh, g_Kh);
    cudaGetSymbolAddress((void**)&Kl, g_Kl);
    cudaGetSymbolAddress((void**)&Vth, g_Vth);
    cudaGetSymbolAddress((void**)&Vtl, g_Vtl);
    cudaGetSymbolAddress((void**)&Ph, g_Ph);
    cudaGetSymbolAddress((void**)&Pl, g_Pl);
    cudaGetSymbolAddress((void**)&rowsum, g_rowsum);

    cudaFuncSetAttribute(gemm_sp3, cudaFuncAttributeMaxDynamicSharedMemorySize, 98304);
    cudaFuncSetAttribute(qkv_fused, cudaFuncAttributeMaxDynamicSharedMemorySize, 98304);

    size_t nx = (size_t)N_TOK * DIM;
    split_f32<<<(unsigned)((nx + 255) / 256), 256>>>(X, Xh, Xl, nx);
    size_t nw = (size_t)DIM * DIM;
    unsigned gw = (unsigned)((nw + 255) / 256);
    split_f32<<<gw, 256>>>(Wq, Wqh, Wql, nw);
    split_f32<<<gw, 256>>>(Wk, Wkh, Wkl, nw);
    split_f32<<<gw, 256>>>(Wv, Wvh, Wvl, nw);
    zero_f32<<<N_TOK / 256, 256>>>(rowsum, N_TOK);

    dim3 blk(256, 1, 1);

    // Q, K, Vt in one fused launch
    dim3 gqkv(DIM / 128, N_TOK / 128, 3);
    qkv_fused<<<gqkv, blk, 98304>>>(Xh, Xl, Wqh, Wql, Wkh, Wkl, Wvh, Wvl,
                                    Qh, Ql, Kh, Kl, Vth, Vtl);

    // P~ = exp(Q K^T - 40) : M=8192, N=8192, K=1024; split out + rowsum
    dim3 gs(N_TOK / 128, N_TOK / 128, 1);
    gemm_sp3<<<gs, blk, 98304>>>(Qh, Ql, Kh, Kl, (float*)0, Ph, Pl, rowsum, N_TOK, DIM, 2);

    // O = (P~ Vt^T) / rowsum : M=8192, N=1024, K=8192; scaled fp32 out
    dim3 go(DIM / 128, N_TOK / 128, 1);
    gemm_sp3<<<go, blk, 98304>>>(Ph, Pl, Vth, Vtl, O, (bf16*)0, (bf16*)0, rowsum, DIM, N_TOK, 3);
}